// round 3
// baseline (speedup 1.0000x reference)
#include <cuda_runtime.h>

// Problem constants (fixed by the reference).
#define Bv 2
#define Cv 48
#define Hv 80
#define Wv 128
#define MDv 4
#define RANGEv 81          // (2*MD+1)^2
#define HWv (Hv * Wv)      // 10240
#define CHWv (Cv * HWv)    // 491520

// Per-pixel inverse L2 norms.
__device__ float g_rn1[Bv * HWv];
__device__ float g_rn2[Bv * HWv];

// Quad-packed normalized features (fp32, exact). Entry (b,c,y,x):
//   .x = v[y ][x]   .y = v[y ][x1]
//   .z = v[y1][x]   .w = v[y1][x1]   with x1=min(x+1,W-1), y1=min(y+1,H-1)
__device__ float4 g_q1[Bv * CHWv];   // normalized feature1 (backward source)
__device__ float4 g_q2[Bv * CHWv];   // normalized feature2 (forward source)

// ---------------------------------------------------------------------------
// Kernel 1: per-pixel inverse norms. Block = 64 pixels x 4 channel-groups.
// ---------------------------------------------------------------------------
__global__ __launch_bounds__(256)
void rnorm_kernel(const float* __restrict__ f1,
                  const float* __restrict__ f2) {
    __shared__ float sm1[256];
    __shared__ float sm2[256];
    const int tid = threadIdx.x;
    const int pix = tid & 63;           // pixel within block
    const int grp = tid >> 6;           // channel group 0..3 (12 ch each)
    const int p = blockIdx.x * 64 + pix;

    float s1 = 0.f, s2 = 0.f;
    if (p < Bv * HWv) {
        const int b = p / HWv;
        const int hw = p - b * HWv;
        const float* a1 = f1 + b * CHWv + hw + grp * 12 * HWv;
        const float* a2 = f2 + b * CHWv + hw + grp * 12 * HWv;
#pragma unroll
        for (int c = 0; c < 12; c++) {
            float v1 = a1[c * HWv];
            float v2 = a2[c * HWv];
            s1 = fmaf(v1, v1, s1);
            s2 = fmaf(v2, v2, s2);
        }
    }
    sm1[tid] = s1; sm2[tid] = s2;
    __syncthreads();
    if (tid < 128) { sm1[tid] += sm1[tid + 128]; sm2[tid] += sm2[tid + 128]; }
    __syncthreads();
    if (tid < 64 && p < Bv * HWv) {
        float t1 = sm1[tid] + sm1[tid + 64];
        float t2 = sm2[tid] + sm2[tid + 64];
        g_rn1[p] = rsqrtf(t1 + 1e-6f);
        g_rn2[p] = rsqrtf(t2 + 1e-6f);
    }
}

// ---------------------------------------------------------------------------
// Kernel 2: build fp32 quad-packed normalized features.
// ---------------------------------------------------------------------------
__global__ __launch_bounds__(256)
void pack_kernel(const float* __restrict__ f1,
                 const float* __restrict__ f2) {
    int n = blockIdx.x * blockDim.x + threadIdx.x;
    if (n >= Bv * CHWv) return;
    int x = n & (Wv - 1);
    int t = n >> 7;            // (b*C + c)*H + y
    int y = t % Hv;
    int bc = t / Hv;           // b*C + c
    int b = bc / Cv;

    int x1 = min(x + 1, Wv - 1);
    int y1 = min(y + 1, Hv - 1);

    int rbase = b * HWv;
    float rnA00 = g_rn1[rbase + y * Wv + x];
    float rnA01 = g_rn1[rbase + y * Wv + x1];
    float rnA10 = g_rn1[rbase + y1 * Wv + x];
    float rnA11 = g_rn1[rbase + y1 * Wv + x1];
    float rnB00 = g_rn2[rbase + y * Wv + x];
    float rnB01 = g_rn2[rbase + y * Wv + x1];
    float rnB10 = g_rn2[rbase + y1 * Wv + x];
    float rnB11 = g_rn2[rbase + y1 * Wv + x1];

    int cbase = bc * HWv;
    float4 qa, qb;
    qa.x = f1[cbase + y * Wv + x]   * rnA00;
    qa.y = f1[cbase + y * Wv + x1]  * rnA01;
    qa.z = f1[cbase + y1 * Wv + x]  * rnA10;
    qa.w = f1[cbase + y1 * Wv + x1] * rnA11;
    qb.x = f2[cbase + y * Wv + x]   * rnB00;
    qb.y = f2[cbase + y * Wv + x1]  * rnB01;
    qb.z = f2[cbase + y1 * Wv + x]  * rnB10;
    qb.w = f2[cbase + y1 * Wv + x1] * rnB11;
    g_q1[n] = qa;
    g_q2[n] = qb;
}

// ---------------------------------------------------------------------------
// Per-axis sampling, replicating the reference exactly:
//   g = 2*v/(D-1) - 1 ; ix = ((g+1)*D - 1) * 0.5
// ---------------------------------------------------------------------------
__device__ __forceinline__ void axis_sample(float v, int D,
                                            int& i0, float& wf, float& mv) {
    float g = (2.0f * v) / (float)(D - 1) - 1.0f;
    float ix = ((g + 1.0f) * (float)D - 1.0f) * 0.5f;

    float ixb = fminf(fmaxf(ix, 0.0f), (float)(D - 1));
    float x0f = floorf(ixb);
    wf = ixb - x0f;
    i0 = (int)x0f;

    float fx = floorf(ix);
    float mw = ix - fx;
    float in0 = (fx >= 0.0f && fx <= (float)(D - 1)) ? 1.0f : 0.0f;
    float in1 = (fx + 1.0f >= 0.0f && fx + 1.0f <= (float)(D - 1)) ? 1.0f : 0.0f;
    mv = (1.0f - mw) * in0 + mw * in1;
}

// ---------------------------------------------------------------------------
// Kernel 3: cost volume. Block (32 w, 9 dv); thread loops 9 du.
// t = 0.5 => forward disp = +d (samples f2), backward = -d (samples f1).
// ---------------------------------------------------------------------------
__global__ __launch_bounds__(288, 3)
void costvol_kernel(const float* __restrict__ BM, float* __restrict__ out) {
    const int w = (blockIdx.x << 5) + threadIdx.x;
    const int dvi = threadIdx.y;           // 0..8
    const int h = blockIdx.y;
    const int b = blockIdx.z;

    const float bmx = BM[((b * 2 + 0) * Hv + h) * Wv + w];
    const float bmy = BM[((b * 2 + 1) * Hv + h) * Wv + w];
    const float dytot = bmy + (float)(dvi - MDv);

    int y0f, y0b;
    float wyf, wyb, mvyf, mvyb;
    axis_sample((float)h + dytot, Hv, y0f, wyf, mvyf);
    axis_sample((float)h - dytot, Hv, y0b, wyb, mvyb);

    const float4* __restrict__ pf = g_q2 + b * CHWv + y0f * Wv;  // forward src
    const float4* __restrict__ pb = g_q1 + b * CHWv + y0b * Wv;  // backward src

    const float omwyf = 1.0f - wyf;
    const float omwyb = 1.0f - wyb;

    const int obase = ((b * RANGEv + dvi * 9) * Hv + h) * Wv + w;

#pragma unroll
    for (int dui = 0; dui < 9; dui++) {
        const float dxtot = bmx + (float)(dui - MDv);

        int x0f, x0b;
        float wxf, wxb, mvxf, mvxb;
        axis_sample((float)w + dxtot, Wv, x0f, wxf, mvxf);
        axis_sample((float)w - dxtot, Wv, x0b, wxb, mvxb);

        const float maskf = (mvxf * mvyf < 0.999f) ? 0.0f : 1.0f;
        const float maskb = (mvxb * mvyb < 0.999f) ? 0.0f : 1.0f;

        float acc0 = 0.0f, acc1 = 0.0f;
        if (maskf * maskb != 0.0f) {
            const float f00 = (1.0f - wxf) * omwyf;
            const float f01 = wxf * omwyf;
            const float f10 = (1.0f - wxf) * wyf;
            const float f11 = wxf * wyf;
            const float g00 = (1.0f - wxb) * omwyb;
            const float g01 = wxb * omwyb;
            const float g10 = (1.0f - wxb) * wyb;
            const float g11 = wxb * wyb;

            const float4* qf = pf + x0f;
            const float4* qb = pb + x0b;

#pragma unroll 2
            for (int c = 0; c < Cv; c += 2) {
                const float4 uf0 = qf[c * HWv];
                const float4 ub0 = qb[c * HWv];
                const float4 uf1 = qf[(c + 1) * HWv];
                const float4 ub1 = qb[(c + 1) * HWv];

                float fw0 = f00 * uf0.x;
                fw0 = fmaf(f01, uf0.y, fw0);
                fw0 = fmaf(f10, uf0.z, fw0);
                fw0 = fmaf(f11, uf0.w, fw0);
                float bw0 = g00 * ub0.x;
                bw0 = fmaf(g01, ub0.y, bw0);
                bw0 = fmaf(g10, ub0.z, bw0);
                bw0 = fmaf(g11, ub0.w, bw0);
                acc0 = fmaf(fw0, bw0, acc0);

                float fw1 = f00 * uf1.x;
                fw1 = fmaf(f01, uf1.y, fw1);
                fw1 = fmaf(f10, uf1.z, fw1);
                fw1 = fmaf(f11, uf1.w, fw1);
                float bw1 = g00 * ub1.x;
                bw1 = fmaf(g01, ub1.y, bw1);
                bw1 = fmaf(g10, ub1.z, bw1);
                bw1 = fmaf(g11, ub1.w, bw1);
                acc1 = fmaf(fw1, bw1, acc1);
            }
        }
        out[obase + dui * Hv * Wv] = acc0 + acc1;
    }
}

// ---------------------------------------------------------------------------
extern "C" void kernel_launch(void* const* d_in, const int* in_sizes, int n_in,
                              void* d_out, int out_size) {
    int bm_idx = 2;
    for (int i = 0; i < n_in; i++)
        if (in_sizes[i] == Bv * 2 * Hv * Wv) bm_idx = i;
    int fidx[2], k = 0;
    for (int i = 0; i < n_in && k < 2; i++)
        if (i != bm_idx) fidx[k++] = i;

    const float* f1 = (const float*)d_in[fidx[0]];
    const float* f2 = (const float*)d_in[fidx[1]];
    const float* BM = (const float*)d_in[bm_idx];
    float* out = (float*)d_out;

    rnorm_kernel<<<(Bv * HWv + 63) / 64, 256>>>(f1, f2);
    pack_kernel<<<(Bv * CHWv + 255) / 256, 256>>>(f1, f2);

    dim3 grid(Wv / 32, Hv, Bv);
    dim3 blk(32, 9);
    costvol_kernel<<<grid, blk>>>(BM, out);
}

// round 4
// speedup vs baseline: 1.7646x; 1.7646x over previous
#include <cuda_runtime.h>
#include <cuda_fp16.h>

// Problem constants (fixed by the reference).
#define Bv 2
#define Cv 48
#define Hv 80
#define Wv 128
#define MDv 4
#define RANGEv 81          // (2*MD+1)^2
#define HWv (Hv * Wv)      // 10240
#define CHWv (Cv * HWv)    // 491520

// Per-pixel inverse L2 norms.
__device__ float g_rn1[Bv * HWv];
__device__ float g_rn2[Bv * HWv];

// Quad-packed normalized features (fp16). Entry (b,c,y,x):
//   .x = half2( v[y ][x], v[y ][x1] )
//   .y = half2( v[y1][x], v[y1][x1] )  with x1=min(x+1,W-1), y1=min(y+1,H-1)
__device__ uint2 g_q1[Bv * CHWv];   // normalized feature1 (backward source)
__device__ uint2 g_q2[Bv * CHWv];   // normalized feature2 (forward source)

// ---------------------------------------------------------------------------
// Kernel 1: per-pixel inverse norms. Block = 64 pixels x 4 channel-groups.
// ---------------------------------------------------------------------------
__global__ __launch_bounds__(256)
void rnorm_kernel(const float* __restrict__ f1,
                  const float* __restrict__ f2) {
    __shared__ float sm1[256];
    __shared__ float sm2[256];
    const int tid = threadIdx.x;
    const int pix = tid & 63;
    const int grp = tid >> 6;           // 0..3, 12 channels each
    const int p = blockIdx.x * 64 + pix;

    float s1 = 0.f, s2 = 0.f;
    if (p < Bv * HWv) {
        const int b = p / HWv;
        const int hw = p - b * HWv;
        const float* a1 = f1 + b * CHWv + hw + grp * 12 * HWv;
        const float* a2 = f2 + b * CHWv + hw + grp * 12 * HWv;
#pragma unroll
        for (int c = 0; c < 12; c++) {
            float v1 = a1[c * HWv];
            float v2 = a2[c * HWv];
            s1 = fmaf(v1, v1, s1);
            s2 = fmaf(v2, v2, s2);
        }
    }
    sm1[tid] = s1; sm2[tid] = s2;
    __syncthreads();
    if (tid < 128) { sm1[tid] += sm1[tid + 128]; sm2[tid] += sm2[tid + 128]; }
    __syncthreads();
    if (tid < 64 && p < Bv * HWv) {
        float t1 = sm1[tid] + sm1[tid + 64];
        float t2 = sm2[tid] + sm2[tid + 64];
        g_rn1[p] = rsqrtf(t1 + 1e-6f);
        g_rn2[p] = rsqrtf(t2 + 1e-6f);
    }
}

// ---------------------------------------------------------------------------
// Kernel 2: build fp16 quad-packed normalized features.
// ---------------------------------------------------------------------------
__global__ __launch_bounds__(256)
void pack_kernel(const float* __restrict__ f1,
                 const float* __restrict__ f2) {
    int n = blockIdx.x * blockDim.x + threadIdx.x;
    if (n >= Bv * CHWv) return;
    int x = n & (Wv - 1);
    int t = n >> 7;            // (b*C + c)*H + y
    int y = t % Hv;
    int bc = t / Hv;
    int b = bc / Cv;

    int x1 = min(x + 1, Wv - 1);
    int y1 = min(y + 1, Hv - 1);

    int rbase = b * HWv;
    float rnA00 = g_rn1[rbase + y * Wv + x];
    float rnA01 = g_rn1[rbase + y * Wv + x1];
    float rnA10 = g_rn1[rbase + y1 * Wv + x];
    float rnA11 = g_rn1[rbase + y1 * Wv + x1];
    float rnB00 = g_rn2[rbase + y * Wv + x];
    float rnB01 = g_rn2[rbase + y * Wv + x1];
    float rnB10 = g_rn2[rbase + y1 * Wv + x];
    float rnB11 = g_rn2[rbase + y1 * Wv + x1];

    int cbase = bc * HWv;
    float a00 = f1[cbase + y * Wv + x]   * rnA00;
    float a01 = f1[cbase + y * Wv + x1]  * rnA01;
    float a10 = f1[cbase + y1 * Wv + x]  * rnA10;
    float a11 = f1[cbase + y1 * Wv + x1] * rnA11;
    float b00 = f2[cbase + y * Wv + x]   * rnB00;
    float b01 = f2[cbase + y * Wv + x1]  * rnB01;
    float b10 = f2[cbase + y1 * Wv + x]  * rnB10;
    float b11 = f2[cbase + y1 * Wv + x1] * rnB11;

    uint2 q1, q2;
    *reinterpret_cast<half2*>(&q1.x) = __floats2half2_rn(a00, a01);
    *reinterpret_cast<half2*>(&q1.y) = __floats2half2_rn(a10, a11);
    *reinterpret_cast<half2*>(&q2.x) = __floats2half2_rn(b00, b01);
    *reinterpret_cast<half2*>(&q2.y) = __floats2half2_rn(b10, b11);
    g_q1[n] = q1;
    g_q2[n] = q2;
}

// ---------------------------------------------------------------------------
// Per-axis sampling, replicating the reference arithmetic order exactly:
//   g = 2*v/(D-1) - 1 ; ix = ((g+1)*D - 1) * 0.5
// ---------------------------------------------------------------------------
__device__ __forceinline__ void axis_sample(float v, int D,
                                            int& i0, float& wf, float& mv) {
    float g = (2.0f * v) / (float)(D - 1) - 1.0f;
    float ix = ((g + 1.0f) * (float)D - 1.0f) * 0.5f;

    float ixb = fminf(fmaxf(ix, 0.0f), (float)(D - 1));
    float x0f = floorf(ixb);
    wf = ixb - x0f;
    i0 = (int)x0f;

    float fx = floorf(ix);
    float mw = ix - fx;
    float in0 = (fx >= 0.0f && fx <= (float)(D - 1)) ? 1.0f : 0.0f;
    float in1 = (fx + 1.0f >= 0.0f && fx + 1.0f <= (float)(D - 1)) ? 1.0f : 0.0f;
    mv = (1.0f - mw) * in0 + mw * in1;
}

// Accumulate one channel's contribution from two quads.
__device__ __forceinline__ void quad_acc(uint2 uf, uint2 ub,
                                         float f00, float f01, float f10, float f11,
                                         float g00, float g01, float g10, float g11,
                                         float& acc) {
    const float2 ft = __half22float2(*reinterpret_cast<const half2*>(&uf.x));
    const float2 fb = __half22float2(*reinterpret_cast<const half2*>(&uf.y));
    const float2 bt = __half22float2(*reinterpret_cast<const half2*>(&ub.x));
    const float2 bb = __half22float2(*reinterpret_cast<const half2*>(&ub.y));
    float fw = f00 * ft.x;
    fw = fmaf(f01, ft.y, fw);
    fw = fmaf(f10, fb.x, fw);
    fw = fmaf(f11, fb.y, fw);
    float bw = g00 * bt.x;
    bw = fmaf(g01, bt.y, bw);
    bw = fmaf(g10, bb.x, bw);
    bw = fmaf(g11, bb.y, bw);
    acc = fmaf(fw, bw, acc);
}

// ---------------------------------------------------------------------------
// Kernel 3: cost volume. Block (32 w, 9 dv); thread loops 9 du (rolled).
// Channel loop unrolled x4 with batched loads (MLP ~= 8 per lane).
// t = 0.5 => forward disp = +d (samples f2), backward = -d (samples f1).
// ---------------------------------------------------------------------------
__global__ __launch_bounds__(288, 4)
void costvol_kernel(const float* __restrict__ BM, float* __restrict__ out) {
    const int w = (blockIdx.x << 5) + threadIdx.x;
    const int dvi = threadIdx.y;           // 0..8
    const int h = blockIdx.y;
    const int b = blockIdx.z;

    const float bmx = BM[((b * 2 + 0) * Hv + h) * Wv + w];
    const float bmy = BM[((b * 2 + 1) * Hv + h) * Wv + w];
    const float dytot = bmy + (float)(dvi - MDv);

    int y0f, y0b;
    float wyf, wyb, mvyf, mvyb;
    axis_sample((float)h + dytot, Hv, y0f, wyf, mvyf);
    axis_sample((float)h - dytot, Hv, y0b, wyb, mvyb);

    const uint2* __restrict__ pf = g_q2 + b * CHWv + y0f * Wv;  // forward src
    const uint2* __restrict__ pb = g_q1 + b * CHWv + y0b * Wv;  // backward src

    const float omwyf = 1.0f - wyf;
    const float omwyb = 1.0f - wyb;

    float* op = out + ((b * RANGEv + dvi * 9) * Hv + h) * Wv + w;

#pragma unroll 1
    for (int dui = 0; dui < 9; dui++, op += HWv) {
        const float dxtot = bmx + (float)(dui - MDv);

        int x0f, x0b;
        float wxf, wxb, mvxf, mvxb;
        axis_sample((float)w + dxtot, Wv, x0f, wxf, mvxf);
        axis_sample((float)w - dxtot, Wv, x0b, wxb, mvxb);

        float acc = 0.0f;
        if ((mvxf * mvyf >= 0.999f) && (mvxb * mvyb >= 0.999f)) {
            const float f00 = (1.0f - wxf) * omwyf;
            const float f01 = wxf * omwyf;
            const float f10 = (1.0f - wxf) * wyf;
            const float f11 = wxf * wyf;
            const float g00 = (1.0f - wxb) * omwyb;
            const float g01 = wxb * omwyb;
            const float g10 = (1.0f - wxb) * wyb;
            const float g11 = wxb * wyb;

            const uint2* __restrict__ qf = pf + x0f;
            const uint2* __restrict__ qb = pb + x0b;

#pragma unroll
            for (int c0 = 0; c0 < Cv; c0 += 4) {
                // Batch all 8 loads for this group (immediate offsets off qf/qb).
                const uint2 uf0 = qf[(c0 + 0) * HWv];
                const uint2 uf1 = qf[(c0 + 1) * HWv];
                const uint2 uf2 = qf[(c0 + 2) * HWv];
                const uint2 uf3 = qf[(c0 + 3) * HWv];
                const uint2 ub0 = qb[(c0 + 0) * HWv];
                const uint2 ub1 = qb[(c0 + 1) * HWv];
                const uint2 ub2 = qb[(c0 + 2) * HWv];
                const uint2 ub3 = qb[(c0 + 3) * HWv];

                quad_acc(uf0, ub0, f00, f01, f10, f11, g00, g01, g10, g11, acc);
                quad_acc(uf1, ub1, f00, f01, f10, f11, g00, g01, g10, g11, acc);
                quad_acc(uf2, ub2, f00, f01, f10, f11, g00, g01, g10, g11, acc);
                quad_acc(uf3, ub3, f00, f01, f10, f11, g00, g01, g10, g11, acc);
            }
        }
        *op = acc;
    }
}

// ---------------------------------------------------------------------------
extern "C" void kernel_launch(void* const* d_in, const int* in_sizes, int n_in,
                              void* d_out, int out_size) {
    int bm_idx = 2;
    for (int i = 0; i < n_in; i++)
        if (in_sizes[i] == Bv * 2 * Hv * Wv) bm_idx = i;
    int fidx[2], k = 0;
    for (int i = 0; i < n_in && k < 2; i++)
        if (i != bm_idx) fidx[k++] = i;

    const float* f1 = (const float*)d_in[fidx[0]];
    const float* f2 = (const float*)d_in[fidx[1]];
    const float* BM = (const float*)d_in[bm_idx];
    float* out = (float*)d_out;

    rnorm_kernel<<<(Bv * HWv + 63) / 64, 256>>>(f1, f2);
    pack_kernel<<<(Bv * CHWv + 255) / 256, 256>>>(f1, f2);

    dim3 grid(Wv / 32, Hv, Bv);
    dim3 blk(32, 9);
    costvol_kernel<<<grid, blk>>>(BM, out);
}

// round 5
// speedup vs baseline: 2.1655x; 1.2272x over previous
#include <cuda_runtime.h>
#include <cuda_fp16.h>

// Problem constants (fixed by the reference).
#define Bv 2
#define Cv 48
#define Hv 80
#define Wv 128
#define MDv 4
#define RANGEv 81          // (2*MD+1)^2
#define HWv (Hv * Wv)      // 10240
#define CHWv (Cv * HWv)    // 491520

// Per-pixel inverse L2 norms.
__device__ float g_rn1[Bv * HWv];
__device__ float g_rn2[Bv * HWv];

// Quad-packed normalized features (fp16). Entry (b,c,y,x):
//   .x = half2( v[y ][x], v[y ][x1] )
//   .y = half2( v[y1][x], v[y1][x1] )  with x1=min(x+1,W-1), y1=min(y+1,H-1)
__device__ uint2 g_q1[Bv * CHWv];   // normalized feature1 (backward source)
__device__ uint2 g_q2[Bv * CHWv];   // normalized feature2 (forward source)

// ---------------------------------------------------------------------------
// Kernel 1: per-pixel inverse norms. Block = 64 pixels x 4 channel-groups.
// ---------------------------------------------------------------------------
__global__ __launch_bounds__(256)
void rnorm_kernel(const float* __restrict__ f1,
                  const float* __restrict__ f2) {
    __shared__ float sm1[256];
    __shared__ float sm2[256];
    const int tid = threadIdx.x;
    const int pix = tid & 63;
    const int grp = tid >> 6;           // 0..3, 12 channels each
    const int p = blockIdx.x * 64 + pix;

    float s1 = 0.f, s2 = 0.f;
    if (p < Bv * HWv) {
        const int b = p / HWv;
        const int hw = p - b * HWv;
        const float* a1 = f1 + b * CHWv + hw + grp * 12 * HWv;
        const float* a2 = f2 + b * CHWv + hw + grp * 12 * HWv;
#pragma unroll
        for (int c = 0; c < 12; c++) {
            float v1 = a1[c * HWv];
            float v2 = a2[c * HWv];
            s1 = fmaf(v1, v1, s1);
            s2 = fmaf(v2, v2, s2);
        }
    }
    sm1[tid] = s1; sm2[tid] = s2;
    __syncthreads();
    if (tid < 128) { sm1[tid] += sm1[tid + 128]; sm2[tid] += sm2[tid + 128]; }
    __syncthreads();
    if (tid < 64 && p < Bv * HWv) {
        float t1 = sm1[tid] + sm1[tid + 64];
        float t2 = sm2[tid] + sm2[tid + 64];
        g_rn1[p] = rsqrtf(t1 + 1e-6f);
        g_rn2[p] = rsqrtf(t2 + 1e-6f);
    }
}

// ---------------------------------------------------------------------------
// Kernel 2: build fp16 quad-packed normalized features.
// ---------------------------------------------------------------------------
__global__ __launch_bounds__(256)
void pack_kernel(const float* __restrict__ f1,
                 const float* __restrict__ f2) {
    int n = blockIdx.x * blockDim.x + threadIdx.x;
    if (n >= Bv * CHWv) return;
    int x = n & (Wv - 1);
    int t = n >> 7;            // (b*C + c)*H + y
    int y = t % Hv;
    int bc = t / Hv;
    int b = bc / Cv;

    int x1 = min(x + 1, Wv - 1);
    int y1 = min(y + 1, Hv - 1);

    int rbase = b * HWv;
    float rnA00 = g_rn1[rbase + y * Wv + x];
    float rnA01 = g_rn1[rbase + y * Wv + x1];
    float rnA10 = g_rn1[rbase + y1 * Wv + x];
    float rnA11 = g_rn1[rbase + y1 * Wv + x1];
    float rnB00 = g_rn2[rbase + y * Wv + x];
    float rnB01 = g_rn2[rbase + y * Wv + x1];
    float rnB10 = g_rn2[rbase + y1 * Wv + x];
    float rnB11 = g_rn2[rbase + y1 * Wv + x1];

    int cbase = bc * HWv;
    float a00 = f1[cbase + y * Wv + x]   * rnA00;
    float a01 = f1[cbase + y * Wv + x1]  * rnA01;
    float a10 = f1[cbase + y1 * Wv + x]  * rnA10;
    float a11 = f1[cbase + y1 * Wv + x1] * rnA11;
    float b00 = f2[cbase + y * Wv + x]   * rnB00;
    float b01 = f2[cbase + y * Wv + x1]  * rnB01;
    float b10 = f2[cbase + y1 * Wv + x]  * rnB10;
    float b11 = f2[cbase + y1 * Wv + x1] * rnB11;

    uint2 q1, q2;
    *reinterpret_cast<half2*>(&q1.x) = __floats2half2_rn(a00, a01);
    *reinterpret_cast<half2*>(&q1.y) = __floats2half2_rn(a10, a11);
    *reinterpret_cast<half2*>(&q2.x) = __floats2half2_rn(b00, b01);
    *reinterpret_cast<half2*>(&q2.y) = __floats2half2_rn(b10, b11);
    g_q1[n] = q1;
    g_q2[n] = q2;
}

// ---------------------------------------------------------------------------
// Per-axis sampling, replicating the reference arithmetic order exactly:
//   g = 2*v/(D-1) - 1 ; ix = ((g+1)*D - 1) * 0.5
// ---------------------------------------------------------------------------
__device__ __forceinline__ void axis_sample(float v, int D,
                                            int& i0, float& wf, float& mv) {
    float g = (2.0f * v) / (float)(D - 1) - 1.0f;
    float ix = ((g + 1.0f) * (float)D - 1.0f) * 0.5f;

    float ixb = fminf(fmaxf(ix, 0.0f), (float)(D - 1));
    float x0f = floorf(ixb);
    wf = ixb - x0f;
    i0 = (int)x0f;

    float fx = floorf(ix);
    float mw = ix - fx;
    float in0 = (fx >= 0.0f && fx <= (float)(D - 1)) ? 1.0f : 0.0f;
    float in1 = (fx + 1.0f >= 0.0f && fx + 1.0f <= (float)(D - 1)) ? 1.0f : 0.0f;
    mv = (1.0f - mw) * in0 + mw * in1;
}

// ---------------------------------------------------------------------------
// Kernel 3: cost volume. Block (32 w, 9 dv). gridDim.z = B * 3 du-groups;
// each thread handles 3 du values (3x more warps than R2 for latency hiding).
// Inner loop identical to the best (R2) version.
// t = 0.5 => forward disp = +d (samples f2), backward = -d (samples f1).
// ---------------------------------------------------------------------------
__global__ __launch_bounds__(288)
void costvol_kernel(const float* __restrict__ BM, float* __restrict__ out) {
    const int w = (blockIdx.x << 5) + threadIdx.x;
    const int dvi = threadIdx.y;           // 0..8
    const int h = blockIdx.y;
    const int b = blockIdx.z / 3;
    const int dug = blockIdx.z - b * 3;    // du group: handles du in [dug*3, dug*3+3)

    const float bmx = BM[((b * 2 + 0) * Hv + h) * Wv + w];
    const float bmy = BM[((b * 2 + 1) * Hv + h) * Wv + w];
    const float dytot = bmy + (float)(dvi - MDv);

    int y0f, y0b;
    float wyf, wyb, mvyf, mvyb;
    axis_sample((float)h + dytot, Hv, y0f, wyf, mvyf);
    axis_sample((float)h - dytot, Hv, y0b, wyb, mvyb);

    const uint2* __restrict__ pf = g_q2 + b * CHWv + y0f * Wv;  // forward src
    const uint2* __restrict__ pb = g_q1 + b * CHWv + y0b * Wv;  // backward src

    const float omwyf = 1.0f - wyf;
    const float omwyb = 1.0f - wyb;

    const int obase = ((b * RANGEv + dvi * 9 + dug * 3) * Hv + h) * Wv + w;

#pragma unroll
    for (int k = 0; k < 3; k++) {
        const int dui = dug * 3 + k;
        const float dxtot = bmx + (float)(dui - MDv);

        int x0f, x0b;
        float wxf, wxb, mvxf, mvxb;
        axis_sample((float)w + dxtot, Wv, x0f, wxf, mvxf);
        axis_sample((float)w - dxtot, Wv, x0b, wxb, mvxb);

        const float maskf = (mvxf * mvyf < 0.999f) ? 0.0f : 1.0f;
        const float maskb = (mvxb * mvyb < 0.999f) ? 0.0f : 1.0f;

        float acc = 0.0f;
        if (maskf * maskb != 0.0f) {
            const float f00 = (1.0f - wxf) * omwyf;
            const float f01 = wxf * omwyf;
            const float f10 = (1.0f - wxf) * wyf;
            const float f11 = wxf * wyf;
            const float g00 = (1.0f - wxb) * omwyb;
            const float g01 = wxb * omwyb;
            const float g10 = (1.0f - wxb) * wyb;
            const float g11 = wxb * wyb;

            const uint2* qf = pf + x0f;
            const uint2* qb = pb + x0b;

#pragma unroll 6
            for (int c = 0; c < Cv; c++) {
                const uint2 uf = qf[c * HWv];
                const uint2 ub = qb[c * HWv];
                const float2 ft = __half22float2(*reinterpret_cast<const half2*>(&uf.x));
                const float2 fb = __half22float2(*reinterpret_cast<const half2*>(&uf.y));
                const float2 bt = __half22float2(*reinterpret_cast<const half2*>(&ub.x));
                const float2 bb = __half22float2(*reinterpret_cast<const half2*>(&ub.y));

                float fw = f00 * ft.x;
                fw = fmaf(f01, ft.y, fw);
                fw = fmaf(f10, fb.x, fw);
                fw = fmaf(f11, fb.y, fw);
                float bw = g00 * bt.x;
                bw = fmaf(g01, bt.y, bw);
                bw = fmaf(g10, bb.x, bw);
                bw = fmaf(g11, bb.y, bw);
                acc = fmaf(fw, bw, acc);
            }
        }
        out[obase + k * HWv] = acc;
    }
}

// ---------------------------------------------------------------------------
extern "C" void kernel_launch(void* const* d_in, const int* in_sizes, int n_in,
                              void* d_out, int out_size) {
    int bm_idx = 2;
    for (int i = 0; i < n_in; i++)
        if (in_sizes[i] == Bv * 2 * Hv * Wv) bm_idx = i;
    int fidx[2], k = 0;
    for (int i = 0; i < n_in && k < 2; i++)
        if (i != bm_idx) fidx[k++] = i;

    const float* f1 = (const float*)d_in[fidx[0]];
    const float* f2 = (const float*)d_in[fidx[1]];
    const float* BM = (const float*)d_in[bm_idx];
    float* out = (float*)d_out;

    rnorm_kernel<<<(Bv * HWv + 63) / 64, 256>>>(f1, f2);
    pack_kernel<<<(Bv * CHWv + 255) / 256, 256>>>(f1, f2);

    dim3 grid(Wv / 32, Hv, Bv * 3);
    dim3 blk(32, 9);
    costvol_kernel<<<grid, blk>>>(BM, out);
}

// round 6
// speedup vs baseline: 2.6394x; 1.2188x over previous
#include <cuda_runtime.h>
#include <cuda_fp16.h>

// Problem constants (fixed by the reference).
#define Bv 2
#define Cv 48
#define CP 24              // channel pairs
#define Hv 80
#define Wv 128
#define MDv 4
#define RANGEv 81          // (2*MD+1)^2
#define HWv (Hv * Wv)      // 10240
#define CHWv (Cv * HWv)    // 491520

// Per-pixel inverse L2 norms.
__device__ float g_rn1[Bv * HWv];
__device__ float g_rn2[Bv * HWv];

// Channel-pair quad-packed normalized features (fp16).
// Entry (b, c2, y, x) is 16 bytes:
//   .x = half2( v[c0][y ][x], v[c0][y ][x1] )
//   .y = half2( v[c0][y1][x], v[c0][y1][x1] )
//   .z = half2( v[c1][y ][x], v[c1][y ][x1] )
//   .w = half2( v[c1][y1][x], v[c1][y1][x1] )
// with c0=2*c2, c1=c0+1, x1=min(x+1,W-1), y1=min(y+1,H-1).
__device__ uint4 g_p1[Bv * CP * HWv];   // normalized feature1 (backward source)
__device__ uint4 g_p2[Bv * CP * HWv];   // normalized feature2 (forward source)

// ---------------------------------------------------------------------------
// Kernel 1: per-pixel inverse norms. Block = 64 pixels x 4 channel-groups.
// ---------------------------------------------------------------------------
__global__ __launch_bounds__(256)
void rnorm_kernel(const float* __restrict__ f1,
                  const float* __restrict__ f2) {
    __shared__ float sm1[256];
    __shared__ float sm2[256];
    const int tid = threadIdx.x;
    const int pix = tid & 63;
    const int grp = tid >> 6;           // 0..3, 12 channels each
    const int p = blockIdx.x * 64 + pix;

    float s1 = 0.f, s2 = 0.f;
    if (p < Bv * HWv) {
        const int b = p / HWv;
        const int hw = p - b * HWv;
        const float* a1 = f1 + b * CHWv + hw + grp * 12 * HWv;
        const float* a2 = f2 + b * CHWv + hw + grp * 12 * HWv;
#pragma unroll
        for (int c = 0; c < 12; c++) {
            float v1 = a1[c * HWv];
            float v2 = a2[c * HWv];
            s1 = fmaf(v1, v1, s1);
            s2 = fmaf(v2, v2, s2);
        }
    }
    sm1[tid] = s1; sm2[tid] = s2;
    __syncthreads();
    if (tid < 128) { sm1[tid] += sm1[tid + 128]; sm2[tid] += sm2[tid + 128]; }
    __syncthreads();
    if (tid < 64 && p < Bv * HWv) {
        float t1 = sm1[tid] + sm1[tid + 64];
        float t2 = sm2[tid] + sm2[tid + 64];
        g_rn1[p] = rsqrtf(t1 + 1e-6f);
        g_rn2[p] = rsqrtf(t2 + 1e-6f);
    }
}

// ---------------------------------------------------------------------------
// Kernel 2: build channel-pair fp16 quad records.
// One thread per (b, c2, y, x).
// ---------------------------------------------------------------------------
__global__ __launch_bounds__(256)
void pack_kernel(const float* __restrict__ f1,
                 const float* __restrict__ f2) {
    int n = blockIdx.x * blockDim.x + threadIdx.x;
    if (n >= Bv * CP * HWv) return;
    int x = n & (Wv - 1);
    int t = n >> 7;            // (b*CP + c2)*H + y
    int y = t % Hv;
    int bc = t / Hv;           // b*CP + c2
    int b = bc / CP;
    int c2 = bc - b * CP;
    int c0 = 2 * c2;

    int x1 = min(x + 1, Wv - 1);
    int y1 = min(y + 1, Hv - 1);

    int rbase = b * HWv;
    float rnA00 = g_rn1[rbase + y * Wv + x];
    float rnA01 = g_rn1[rbase + y * Wv + x1];
    float rnA10 = g_rn1[rbase + y1 * Wv + x];
    float rnA11 = g_rn1[rbase + y1 * Wv + x1];
    float rnB00 = g_rn2[rbase + y * Wv + x];
    float rnB01 = g_rn2[rbase + y * Wv + x1];
    float rnB10 = g_rn2[rbase + y1 * Wv + x];
    float rnB11 = g_rn2[rbase + y1 * Wv + x1];

    uint4 q1, q2;
#pragma unroll
    for (int k = 0; k < 2; k++) {
        int cbase = (b * Cv + c0 + k) * HWv;
        float a00 = f1[cbase + y * Wv + x]   * rnA00;
        float a01 = f1[cbase + y * Wv + x1]  * rnA01;
        float a10 = f1[cbase + y1 * Wv + x]  * rnA10;
        float a11 = f1[cbase + y1 * Wv + x1] * rnA11;
        float b00 = f2[cbase + y * Wv + x]   * rnB00;
        float b01 = f2[cbase + y * Wv + x1]  * rnB01;
        float b10 = f2[cbase + y1 * Wv + x]  * rnB10;
        float b11 = f2[cbase + y1 * Wv + x1] * rnB11;

        unsigned* q1p = k == 0 ? &q1.x : &q1.z;
        unsigned* q2p = k == 0 ? &q2.x : &q2.z;
        *reinterpret_cast<half2*>(q1p)     = __floats2half2_rn(a00, a01);
        *reinterpret_cast<half2*>(q1p + 1) = __floats2half2_rn(a10, a11);
        *reinterpret_cast<half2*>(q2p)     = __floats2half2_rn(b00, b01);
        *reinterpret_cast<half2*>(q2p + 1) = __floats2half2_rn(b10, b11);
    }
    g_p1[n] = q1;
    g_p2[n] = q2;
}

// ---------------------------------------------------------------------------
// Per-axis sampling, replicating the reference arithmetic order exactly:
//   g = 2*v/(D-1) - 1 ; ix = ((g+1)*D - 1) * 0.5
// ---------------------------------------------------------------------------
__device__ __forceinline__ void axis_sample(float v, int D,
                                            int& i0, float& wf, float& mv) {
    float g = (2.0f * v) / (float)(D - 1) - 1.0f;
    float ix = ((g + 1.0f) * (float)D - 1.0f) * 0.5f;

    float ixb = fminf(fmaxf(ix, 0.0f), (float)(D - 1));
    float x0f = floorf(ixb);
    wf = ixb - x0f;
    i0 = (int)x0f;

    float fx = floorf(ix);
    float mw = ix - fx;
    float in0 = (fx >= 0.0f && fx <= (float)(D - 1)) ? 1.0f : 0.0f;
    float in1 = (fx + 1.0f >= 0.0f && fx + 1.0f <= (float)(D - 1)) ? 1.0f : 0.0f;
    mv = (1.0f - mw) * in0 + mw * in1;
}

// Accumulate one channel from two half2-pairs (one quad each).
__device__ __forceinline__ void quad_acc2(unsigned fx_, unsigned fy_,
                                          unsigned bx_, unsigned by_,
                                          float f00, float f01, float f10, float f11,
                                          float g00, float g01, float g10, float g11,
                                          float& acc) {
    const float2 ft = __half22float2(*reinterpret_cast<const half2*>(&fx_));
    const float2 fb = __half22float2(*reinterpret_cast<const half2*>(&fy_));
    const float2 bt = __half22float2(*reinterpret_cast<const half2*>(&bx_));
    const float2 bb = __half22float2(*reinterpret_cast<const half2*>(&by_));
    float fw = f00 * ft.x;
    fw = fmaf(f01, ft.y, fw);
    fw = fmaf(f10, fb.x, fw);
    fw = fmaf(f11, fb.y, fw);
    float bw = g00 * bt.x;
    bw = fmaf(g01, bt.y, bw);
    bw = fmaf(g10, bb.x, bw);
    bw = fmaf(g11, bb.y, bw);
    acc = fmaf(fw, bw, acc);
}

// ---------------------------------------------------------------------------
// Kernel 3: cost volume. Block (32 w, 9 dv). gridDim.z = B * 9 du values;
// each thread computes exactly one output (max concurrency: 51840 warps).
// One LDG.128 per channel-pair per tensor.
// t = 0.5 => forward disp = +d (samples f2), backward = -d (samples f1).
// ---------------------------------------------------------------------------
__global__ __launch_bounds__(288)
void costvol_kernel(const float* __restrict__ BM, float* __restrict__ out) {
    const int w = (blockIdx.x << 5) + threadIdx.x;
    const int dvi = threadIdx.y;           // 0..8
    const int h = blockIdx.y;
    const int b = blockIdx.z / 9;
    const int dui = blockIdx.z - b * 9;    // 0..8

    const float bmx = BM[((b * 2 + 0) * Hv + h) * Wv + w];
    const float bmy = BM[((b * 2 + 1) * Hv + h) * Wv + w];
    const float dytot = bmy + (float)(dvi - MDv);
    const float dxtot = bmx + (float)(dui - MDv);

    int y0f, y0b, x0f, x0b;
    float wyf, wyb, mvyf, mvyb, wxf, wxb, mvxf, mvxb;
    axis_sample((float)h + dytot, Hv, y0f, wyf, mvyf);
    axis_sample((float)h - dytot, Hv, y0b, wyb, mvyb);
    axis_sample((float)w + dxtot, Wv, x0f, wxf, mvxf);
    axis_sample((float)w - dxtot, Wv, x0b, wxb, mvxb);

    float acc0 = 0.0f, acc1 = 0.0f;
    if ((mvxf * mvyf >= 0.999f) && (mvxb * mvyb >= 0.999f)) {
        const float omwyf = 1.0f - wyf;
        const float omwyb = 1.0f - wyb;
        const float f00 = (1.0f - wxf) * omwyf;
        const float f01 = wxf * omwyf;
        const float f10 = (1.0f - wxf) * wyf;
        const float f11 = wxf * wyf;
        const float g00 = (1.0f - wxb) * omwyb;
        const float g01 = wxb * omwyb;
        const float g10 = (1.0f - wxb) * wyb;
        const float g11 = wxb * wyb;

        const uint4* __restrict__ qf = g_p2 + b * CP * HWv + y0f * Wv + x0f;
        const uint4* __restrict__ qb = g_p1 + b * CP * HWv + y0b * Wv + x0b;

#pragma unroll 4
        for (int c2 = 0; c2 < CP; c2++) {
            const uint4 uf = qf[c2 * HWv];
            const uint4 ub = qb[c2 * HWv];
            quad_acc2(uf.x, uf.y, ub.x, ub.y,
                      f00, f01, f10, f11, g00, g01, g10, g11, acc0);
            quad_acc2(uf.z, uf.w, ub.z, ub.w,
                      f00, f01, f10, f11, g00, g01, g10, g11, acc1);
        }
    }
    out[((b * RANGEv + dvi * 9 + dui) * Hv + h) * Wv + w] = acc0 + acc1;
}

// ---------------------------------------------------------------------------
extern "C" void kernel_launch(void* const* d_in, const int* in_sizes, int n_in,
                              void* d_out, int out_size) {
    int bm_idx = 2;
    for (int i = 0; i < n_in; i++)
        if (in_sizes[i] == Bv * 2 * Hv * Wv) bm_idx = i;
    int fidx[2], k = 0;
    for (int i = 0; i < n_in && k < 2; i++)
        if (i != bm_idx) fidx[k++] = i;

    const float* f1 = (const float*)d_in[fidx[0]];
    const float* f2 = (const float*)d_in[fidx[1]];
    const float* BM = (const float*)d_in[bm_idx];
    float* out = (float*)d_out;

    rnorm_kernel<<<(Bv * HWv + 63) / 64, 256>>>(f1, f2);
    pack_kernel<<<(Bv * CP * HWv + 255) / 256, 256>>>(f1, f2);

    dim3 grid(Wv / 32, Hv, Bv * 9);
    dim3 blk(32, 9);
    costvol_kernel<<<grid, blk>>>(BM, out);
}

// round 8
// speedup vs baseline: 2.7677x; 1.0486x over previous
#include <cuda_runtime.h>
#include <cuda_fp16.h>

// Problem constants (fixed by the reference).
#define Bv 2
#define Cv 48
#define CP 24              // channel pairs
#define Hv 80
#define Wv 128
#define MDv 4
#define RANGEv 81          // (2*MD+1)^2
#define HWv (Hv * Wv)      // 10240
#define CHWv (Cv * HWv)    // 491520

// Per-pixel inverse L2 norms.
__device__ float g_rn1[Bv * HWv];
__device__ float g_rn2[Bv * HWv];

// Channel-pair quad-packed normalized features (fp16).
// Entry (b, c2, y, x) is 16 bytes:
//   .x = half2( v[c0][y ][x], v[c0][y ][x1] )
//   .y = half2( v[c0][y1][x], v[c0][y1][x1] )
//   .z = half2( v[c1][y ][x], v[c1][y ][x1] )
//   .w = half2( v[c1][y1][x], v[c1][y1][x1] )
// with c0=2*c2, c1=c0+1, x1=min(x+1,W-1), y1=min(y+1,H-1).
__device__ uint4 g_p1[Bv * CP * HWv];   // normalized feature1 (backward source)
__device__ uint4 g_p2[Bv * CP * HWv];   // normalized feature2 (forward source)

// ---------------------------------------------------------------------------
// Kernel 1: per-pixel inverse norms. Block = 64 pixels x 4 channel-groups.
// ---------------------------------------------------------------------------
__global__ __launch_bounds__(256)
void rnorm_kernel(const float* __restrict__ f1,
                  const float* __restrict__ f2) {
    __shared__ float sm1[256];
    __shared__ float sm2[256];
    const int tid = threadIdx.x;
    const int pix = tid & 63;
    const int grp = tid >> 6;           // 0..3, 12 channels each
    const int p = blockIdx.x * 64 + pix;

    float s1 = 0.f, s2 = 0.f;
    if (p < Bv * HWv) {
        const int b = p / HWv;
        const int hw = p - b * HWv;
        const float* a1 = f1 + b * CHWv + hw + grp * 12 * HWv;
        const float* a2 = f2 + b * CHWv + hw + grp * 12 * HWv;
#pragma unroll
        for (int c = 0; c < 12; c++) {
            float v1 = a1[c * HWv];
            float v2 = a2[c * HWv];
            s1 = fmaf(v1, v1, s1);
            s2 = fmaf(v2, v2, s2);
        }
    }
    sm1[tid] = s1; sm2[tid] = s2;
    __syncthreads();
    if (tid < 128) { sm1[tid] += sm1[tid + 128]; sm2[tid] += sm2[tid + 128]; }
    __syncthreads();
    if (tid < 64 && p < Bv * HWv) {
        float t1 = sm1[tid] + sm1[tid + 64];
        float t2 = sm2[tid] + sm2[tid + 64];
        g_rn1[p] = rsqrtf(t1 + 1e-6f);
        g_rn2[p] = rsqrtf(t2 + 1e-6f);
    }
}

// ---------------------------------------------------------------------------
// Kernel 2: build channel-pair fp16 quad records.
// One thread per (b, c2, y, x).
// ---------------------------------------------------------------------------
__global__ __launch_bounds__(256)
void pack_kernel(const float* __restrict__ f1,
                 const float* __restrict__ f2) {
    int n = blockIdx.x * blockDim.x + threadIdx.x;
    if (n >= Bv * CP * HWv) return;
    int x = n & (Wv - 1);
    int t = n >> 7;            // (b*CP + c2)*H + y
    int y = t % Hv;
    int bc = t / Hv;           // b*CP + c2
    int b = bc / CP;
    int c2 = bc - b * CP;
    int c0 = 2 * c2;

    int x1 = min(x + 1, Wv - 1);
    int y1 = min(y + 1, Hv - 1);

    int rbase = b * HWv;
    float rnA00 = g_rn1[rbase + y * Wv + x];
    float rnA01 = g_rn1[rbase + y * Wv + x1];
    float rnA10 = g_rn1[rbase + y1 * Wv + x];
    float rnA11 = g_rn1[rbase + y1 * Wv + x1];
    float rnB00 = g_rn2[rbase + y * Wv + x];
    float rnB01 = g_rn2[rbase + y * Wv + x1];
    float rnB10 = g_rn2[rbase + y1 * Wv + x];
    float rnB11 = g_rn2[rbase + y1 * Wv + x1];

    uint4 q1, q2;
#pragma unroll
    for (int k = 0; k < 2; k++) {
        int cbase = (b * Cv + c0 + k) * HWv;
        float a00 = f1[cbase + y * Wv + x]   * rnA00;
        float a01 = f1[cbase + y * Wv + x1]  * rnA01;
        float a10 = f1[cbase + y1 * Wv + x]  * rnA10;
        float a11 = f1[cbase + y1 * Wv + x1] * rnA11;
        float b00 = f2[cbase + y * Wv + x]   * rnB00;
        float b01 = f2[cbase + y * Wv + x1]  * rnB01;
        float b10 = f2[cbase + y1 * Wv + x]  * rnB10;
        float b11 = f2[cbase + y1 * Wv + x1] * rnB11;

        unsigned* q1p = k == 0 ? &q1.x : &q1.z;
        unsigned* q2p = k == 0 ? &q2.x : &q2.z;
        *reinterpret_cast<half2*>(q1p)     = __floats2half2_rn(a00, a01);
        *reinterpret_cast<half2*>(q1p + 1) = __floats2half2_rn(a10, a11);
        *reinterpret_cast<half2*>(q2p)     = __floats2half2_rn(b00, b01);
        *reinterpret_cast<half2*>(q2p + 1) = __floats2half2_rn(b10, b11);
    }
    g_p1[n] = q1;
    g_p2[n] = q2;
}

// ---------------------------------------------------------------------------
// Per-axis sampling, replicating the reference arithmetic order exactly:
//   g = 2*v/(D-1) - 1 ; ix = ((g+1)*D - 1) * 0.5
// ---------------------------------------------------------------------------
__device__ __forceinline__ void axis_sample(float v, int D,
                                            int& i0, float& wf, float& mv) {
    float g = (2.0f * v) / (float)(D - 1) - 1.0f;
    float ix = ((g + 1.0f) * (float)D - 1.0f) * 0.5f;

    float ixb = fminf(fmaxf(ix, 0.0f), (float)(D - 1));
    float x0f = floorf(ixb);
    wf = ixb - x0f;
    i0 = (int)x0f;

    float fx = floorf(ix);
    float mw = ix - fx;
    float in0 = (fx >= 0.0f && fx <= (float)(D - 1)) ? 1.0f : 0.0f;
    float in1 = (fx + 1.0f >= 0.0f && fx + 1.0f <= (float)(D - 1)) ? 1.0f : 0.0f;
    mv = (1.0f - mw) * in0 + mw * in1;
}

// Accumulate one channel from two half2-pairs (one quad each).
__device__ __forceinline__ void quad_acc2(unsigned fx_, unsigned fy_,
                                          unsigned bx_, unsigned by_,
                                          float f00, float f01, float f10, float f11,
                                          float g00, float g01, float g10, float g11,
                                          float& acc) {
    const float2 ft = __half22float2(*reinterpret_cast<const half2*>(&fx_));
    const float2 fb = __half22float2(*reinterpret_cast<const half2*>(&fy_));
    const float2 bt = __half22float2(*reinterpret_cast<const half2*>(&bx_));
    const float2 bb = __half22float2(*reinterpret_cast<const half2*>(&by_));
    float fw = f00 * ft.x;
    fw = fmaf(f01, ft.y, fw);
    fw = fmaf(f10, fb.x, fw);
    fw = fmaf(f11, fb.y, fw);
    float bw = g00 * bt.x;
    bw = fmaf(g01, bt.y, bw);
    bw = fmaf(g10, bb.x, bw);
    bw = fmaf(g11, bb.y, bw);
    acc = fmaf(fw, bw, acc);
}

// ---------------------------------------------------------------------------
// Kernel 3: cost volume. Block (32 w, 9 du) with dv FIXED per block
// (gridDim.z = B * 9 dv values). All 288 threads of a block sample nearly the
// same y-rows (dv fixed; only bmy jitter varies) and overlapping x windows,
// so the block's tap working set (~136 KB) fits L1 -> minimal L2 traffic.
// One LDG.128 per channel-pair per tensor.
// t = 0.5 => forward disp = +d (samples f2), backward = -d (samples f1).
// ---------------------------------------------------------------------------
__global__ __launch_bounds__(288)
void costvol_kernel(const float* __restrict__ BM, float* __restrict__ out) {
    const int w = (blockIdx.x << 5) + threadIdx.x;
    const int dui = threadIdx.y;           // 0..8  (du varies within block)
    const int h = blockIdx.y;
    const int b = blockIdx.z / 9;
    const int dvi = blockIdx.z - b * 9;    // 0..8  (dv fixed per block)

    const float bmx = BM[((b * 2 + 0) * Hv + h) * Wv + w];
    const float bmy = BM[((b * 2 + 1) * Hv + h) * Wv + w];
    const float dytot = bmy + (float)(dvi - MDv);
    const float dxtot = bmx + (float)(dui - MDv);

    int y0f, y0b, x0f, x0b;
    float wyf, wyb, mvyf, mvyb, wxf, wxb, mvxf, mvxb;
    axis_sample((float)h + dytot, Hv, y0f, wyf, mvyf);
    axis_sample((float)h - dytot, Hv, y0b, wyb, mvyb);
    axis_sample((float)w + dxtot, Wv, x0f, wxf, mvxf);
    axis_sample((float)w - dxtot, Wv, x0b, wxb, mvxb);

    float acc0 = 0.0f, acc1 = 0.0f;
    if ((mvxf * mvyf >= 0.999f) && (mvxb * mvyb >= 0.999f)) {
        const float omwyf = 1.0f - wyf;
        const float omwyb = 1.0f - wyb;
        const float f00 = (1.0f - wxf) * omwyf;
        const float f01 = wxf * omwyf;
        const float f10 = (1.0f - wxf) * wyf;
        const float f11 = wxf * wyf;
        const float g00 = (1.0f - wxb) * omwyb;
        const float g01 = wxb * omwyb;
        const float g10 = (1.0f - wxb) * wyb;
        const float g11 = wxb * wyb;

        const uint4* __restrict__ qf = g_p2 + b * CP * HWv + y0f * Wv + x0f;
        const uint4* __restrict__ qb = g_p1 + b * CP * HWv + y0b * Wv + x0b;

#pragma unroll 4
        for (int c2 = 0; c2 < CP; c2++) {
            const uint4 uf = qf[c2 * HWv];
            const uint4 ub = qb[c2 * HWv];
            quad_acc2(uf.x, uf.y, ub.x, ub.y,
                      f00, f01, f10, f11, g00, g01, g10, g11, acc0);
            quad_acc2(uf.z, uf.w, ub.z, ub.w,
                      f00, f01, f10, f11, g00, g01, g10, g11, acc1);
        }
    }
    out[((b * RANGEv + dvi * 9 + dui) * Hv + h) * Wv + w] = acc0 + acc1;
}

// ---------------------------------------------------------------------------
extern "C" void kernel_launch(void* const* d_in, const int* in_sizes, int n_in,
                              void* d_out, int out_size) {
    int bm_idx = 2;
    for (int i = 0; i < n_in; i++)
        if (in_sizes[i] == Bv * 2 * Hv * Wv) bm_idx = i;
    int fidx[2], k = 0;
    for (int i = 0; i < n_in && k < 2; i++)
        if (i != bm_idx) fidx[k++] = i;

    const float* f1 = (const float*)d_in[fidx[0]];
    const float* f2 = (const float*)d_in[fidx[1]];
    const float* BM = (const float*)d_in[bm_idx];
    float* out = (float*)d_out;

    rnorm_kernel<<<(Bv * HWv + 63) / 64, 256>>>(f1, f2);
    pack_kernel<<<(Bv * CP * HWv + 255) / 256, 256>>>(f1, f2);

    dim3 grid(Wv / 32, Hv, Bv * 9);
    dim3 blk(32, 9);
    costvol_kernel<<<grid, blk>>>(BM, out);
}